// round 5
// baseline (speedup 1.0000x reference)
#include <cuda_runtime.h>

#define N_NODES 100000
#define N_EDGES 1000000
#define D 64

// Scratch accumulator: agg = features + scatter_add(messages).
// float4 => 16B alignment for vector stores / red.global.add.v4.f32.
__device__ float4 g_agg4[N_NODES * (D / 4)];

// Dtype flag for edge_index: 1 = int64, 0 = int32. Set by probe_kernel.
__device__ int g_ei_is64;

// ---------------------------------------------------------------------------
// Probe: decide whether edge_index is int64 or int32.
// If int64 (values < 2^31), every odd 32-bit word is 0. If int32, odd words
// are random node ids (all-zero probability ~1e-5000 over 1024 words).
// ---------------------------------------------------------------------------
__global__ void probe_kernel(const unsigned int* __restrict__ ei_words) {
    if (threadIdx.x == 0 && blockIdx.x == 0) {
        int is64 = 1;
        for (int i = 1; i < 2048; i += 2) {
            if (ei_words[i] != 0u) { is64 = 0; break; }
        }
        g_ei_is64 = is64;
    }
}

// ---------------------------------------------------------------------------
// Kernel 1: agg = features (fuses the residual add).
// ---------------------------------------------------------------------------
__global__ void init_kernel(const float4* __restrict__ feat4) {
    int i = blockIdx.x * blockDim.x + threadIdx.x;
    const int total = N_NODES * (D / 4);
    if (i < total) {
        g_agg4[i] = feat4[i];
    }
}

// ---------------------------------------------------------------------------
// Kernel 2: edge scatter. 16 lanes per edge, one float4 per lane.
//   agg[dst][j] += feat[src][j] * w   via red.global.add.v4.f32 (sm_90+).
// 16 lanes * 16B = 256B contiguous per edge -> fully coalesced gather;
// features (25.6 MB) fits in L2 so the random gather is L2-served.
// ---------------------------------------------------------------------------
__global__ void scatter_kernel(const float4* __restrict__ feat4,
                               const void* __restrict__ edge_index,
                               const float* __restrict__ edge_weight) {
    int gid = blockIdx.x * blockDim.x + threadIdx.x;   // 16M lanes total
    int e = gid >> 4;       // edge id
    int j = gid & 15;       // float4 chunk within the 64-float row
    if (e >= N_EDGES) return;

    int src, dst;
    if (g_ei_is64) {
        const long long* ei = (const long long*)edge_index;
        src = (int)ei[e];
        dst = (int)ei[N_EDGES + e];
    } else {
        const int* ei = (const int*)edge_index;
        src = ei[e];
        dst = ei[N_EDGES + e];
    }
    // Defensive bounds check: skip malformed edges instead of crashing.
    if ((unsigned)src >= N_NODES || (unsigned)dst >= N_NODES) return;

    float w = edge_weight[e];

    float4 f = feat4[src * 16 + j];
    f.x *= w; f.y *= w; f.z *= w; f.w *= w;

    float4* p = g_agg4 + dst * 16 + j;
    asm volatile("red.global.add.v4.f32 [%0], {%1, %2, %3, %4};"
                 :: "l"(p), "f"(f.x), "f"(f.y), "f"(f.z), "f"(f.w)
                 : "memory");
}

// ---------------------------------------------------------------------------
// Kernel 3: out = agg @ W^T + b. Thread-per-node; W transposed into smem so
// the inner loop reads Ws[i*64+o] -- same address across all lanes (broadcast,
// conflict-free). 64 fp32 accumulators per thread.
// ---------------------------------------------------------------------------
__global__ void __launch_bounds__(128) gemm_kernel(const float* __restrict__ W,
                                                   const float* __restrict__ bias,
                                                   float* __restrict__ out) {
    __shared__ float Ws[D * D];   // Ws[i*D + o] = W[o*D + i]
    __shared__ float bs[D];

    int tid = threadIdx.x;
    for (int k = tid; k < D * D; k += blockDim.x) {
        int i = k / D;
        int o = k % D;
        Ws[i * D + o] = W[o * D + i];
    }
    if (tid < D) bs[tid] = bias[tid];
    __syncthreads();

    int node = blockIdx.x * blockDim.x + tid;
    if (node >= N_NODES) return;

    const float4* x4 = g_agg4 + node * 16;
    float x[D];
#pragma unroll
    for (int c = 0; c < 16; c++) {
        float4 v = x4[c];
        x[4*c+0] = v.x; x[4*c+1] = v.y; x[4*c+2] = v.z; x[4*c+3] = v.w;
    }

    float y[D];
#pragma unroll
    for (int o = 0; o < D; o++) y[o] = bs[o];

#pragma unroll 4
    for (int i = 0; i < D; i++) {
        float xi = x[i];
        const float* wrow = &Ws[i * D];
#pragma unroll
        for (int o = 0; o < D; o++) {
            y[o] = fmaf(xi, wrow[o], y[o]);
        }
    }

    float4* outp = reinterpret_cast<float4*>(out + (size_t)node * D);
#pragma unroll
    for (int o = 0; o < D / 4; o++) {
        outp[o] = make_float4(y[4*o], y[4*o+1], y[4*o+2], y[4*o+3]);
    }
}

// ---------------------------------------------------------------------------
extern "C" void kernel_launch(void* const* d_in, const int* in_sizes, int n_in,
                              void* d_out, int out_size) {
    // Resolve inputs by element count (robust to metadata ordering):
    //   features   : 6,400,000 f32
    //   edge_index : 2,000,000 ints (int32 or int64 -- probed at runtime)
    //   edge_weight: 1,000,000 f32
    //   W          : 4,096 f32
    //   b          : 64 f32
    const float* feat = nullptr;
    const void*  ei   = nullptr;
    const float* ew   = nullptr;
    const float* W    = nullptr;
    const float* b    = nullptr;

    for (int i = 0; i < n_in; i++) {
        switch (in_sizes[i]) {
            case 6400000: feat = (const float*)d_in[i]; break;
            case 2000000: ei   = d_in[i];               break;
            case 1000000: ew   = (const float*)d_in[i]; break;
            case 4096:    W    = (const float*)d_in[i]; break;
            case 64:      b    = (const float*)d_in[i]; break;
        }
    }

    float* out = (float*)d_out;
    (void)out_size;

    probe_kernel<<<1, 32>>>((const unsigned int*)ei);

    const int init_total = N_NODES * (D / 4);
    init_kernel<<<(init_total + 255) / 256, 256>>>((const float4*)feat);

    const int scatter_lanes = N_EDGES * 16;
    scatter_kernel<<<(scatter_lanes + 255) / 256, 256>>>((const float4*)feat, ei, ew);

    gemm_kernel<<<(N_NODES + 127) / 128, 128>>>(W, b, out);
}

// round 6
// speedup vs baseline: 1.2548x; 1.2548x over previous
#include <cuda_runtime.h>

#define N_NODES 100000
#define N_EDGES 1000000
#define D 64

// Scratch accumulator: agg = features + scatter_add(messages).
// float4 => 16B alignment for vector stores / red.global.add.v4.f32.
__device__ float4 g_agg4[N_NODES * (D / 4)];

// Dtype flag for edge_index: 1 = int64, 0 = int32. Set by probe_kernel.
__device__ int g_ei_is64;

// ---------------------------------------------------------------------------
// Probe: decide whether edge_index is int64 or int32 (parallel, 1 warp).
// If int64 (values < 2^31), every odd 32-bit word is 0.
// ---------------------------------------------------------------------------
__global__ void probe_kernel(const unsigned int* __restrict__ ei_words) {
    int lane = threadIdx.x;
    // each lane checks 4 odd words -> 128 odd words total
    unsigned int nz = 0;
#pragma unroll
    for (int r = 0; r < 4; r++) {
        nz |= ei_words[2 * (lane + 32 * r) + 1];
    }
    unsigned int any = __ballot_sync(0xFFFFFFFFu, nz != 0u);
    if (lane == 0) g_ei_is64 = (any == 0u) ? 1 : 0;
}

// ---------------------------------------------------------------------------
// Kernel 1: agg = features (fuses the residual add).
// ---------------------------------------------------------------------------
__global__ void init_kernel(const float4* __restrict__ feat4) {
    int i = blockIdx.x * blockDim.x + threadIdx.x;
    const int total = N_NODES * (D / 4);
    if (i < total) {
        g_agg4[i] = feat4[i];
    }
}

// ---------------------------------------------------------------------------
// Kernel 2: edge scatter. 16 lanes per edge, one float4 per lane.
//   agg[dst][j] += feat[src][j] * w   via red.global.add.v4.f32 (sm_90+).
// ---------------------------------------------------------------------------
__global__ void scatter_kernel(const float4* __restrict__ feat4,
                               const void* __restrict__ edge_index,
                               const float* __restrict__ edge_weight) {
    int gid = blockIdx.x * blockDim.x + threadIdx.x;   // 16M lanes total
    int e = gid >> 4;       // edge id
    int j = gid & 15;       // float4 chunk within the 64-float row
    if (e >= N_EDGES) return;

    int src, dst;
    if (g_ei_is64) {
        const long long* ei = (const long long*)edge_index;
        src = (int)ei[e];
        dst = (int)ei[N_EDGES + e];
    } else {
        const int* ei = (const int*)edge_index;
        src = ei[e];
        dst = ei[N_EDGES + e];
    }
    if ((unsigned)src >= N_NODES || (unsigned)dst >= N_NODES) return;

    float w = edge_weight[e];

    float4 f = feat4[src * 16 + j];
    f.x *= w; f.y *= w; f.z *= w; f.w *= w;

    float4* p = g_agg4 + dst * 16 + j;
    asm volatile("red.global.add.v4.f32 [%0], {%1, %2, %3, %4};"
                 :: "l"(p), "f"(f.x), "f"(f.y), "f"(f.z), "f"(f.w)
                 : "memory");
}

// ---------------------------------------------------------------------------
// Kernel 3: out = agg @ W^T + b.
// Register-tiled: block = 128 threads computes a 128-node x 64-out tile.
// Thread (mt, nt): 8 nodes (4 f32x2 pairs along m) x 8 outputs.
// x tile staged TRANSPOSED in smem (xs[k][m]) in two K-halves; pairs of
// consecutive nodes load as 64-bit words => direct f32x2 operands.
// W staged natural with +1 pad (ws[n][65]) => conflict-free copy and
// conflict-free broadcast reads.
// Inner loop per k: 2 LDS.128 + 8 LDS.32 + 8 packs + 32 fma.rn.f32x2.
// ---------------------------------------------------------------------------
__global__ void __launch_bounds__(128) gemm_kernel(const float* __restrict__ W,
                                                   const float* __restrict__ bias,
                                                   float* __restrict__ out) {
    __shared__ float xs[32][128];   // 16 KB: xs[k - half*32][m]
    __shared__ float ws[64][65];    // 16.25 KB: ws[n][k], padded row

    const int tid = threadIdx.x;
    const int nt = tid >> 4;        // 0..7  -> outputs nt*8 .. nt*8+7
    const int mt = tid & 15;        // 0..15 -> nodes   mt*8 .. mt*8+7
    const int base = blockIdx.x * 128;

    // Stage W: ws[n][k] = W[n*64+k]; coalesced read, conflict-free write.
    for (int idx = tid; idx < 4096; idx += 128) {
        ws[idx >> 6][idx & 63] = W[idx];
    }

    // Init accumulators with bias (replicated into both f32x2 lanes).
    unsigned long long acc[8][4];
#pragma unroll
    for (int j = 0; j < 8; j++) {
        float bj = __ldg(&bias[nt * 8 + j]);
        unsigned long long bp;
        asm("mov.b64 %0, {%1, %1};" : "=l"(bp) : "f"(bj));
#pragma unroll
        for (int i = 0; i < 4; i++) acc[j][i] = bp;
    }

    const int my_node = base + tid;
    const bool valid = my_node < N_NODES;

#pragma unroll
    for (int h = 0; h < 2; h++) {
        if (h) __syncthreads();   // protect xs before overwrite
        // Load this K-half of the x tile, transposed. Zero-fill tail nodes.
#pragma unroll
        for (int c = 0; c < 8; c++) {
            float4 v = valid ? g_agg4[my_node * 16 + h * 8 + c]
                             : make_float4(0.f, 0.f, 0.f, 0.f);
            xs[c * 4 + 0][tid] = v.x;
            xs[c * 4 + 1][tid] = v.y;
            xs[c * 4 + 2][tid] = v.z;
            xs[c * 4 + 3][tid] = v.w;
        }
        __syncthreads();

#pragma unroll 8
        for (int kk = 0; kk < 32; kk++) {
            const int k = h * 32 + kk;
            // x pairs: 4 x f32x2 along the node dimension
            ulonglong2 xa = *(const ulonglong2*)&xs[kk][mt * 8];
            ulonglong2 xb = *(const ulonglong2*)&xs[kk][mt * 8 + 4];
            unsigned long long xp0 = xa.x, xp1 = xa.y, xp2 = xb.x, xp3 = xb.y;
#pragma unroll
            for (int j = 0; j < 8; j++) {
                float w = ws[nt * 8 + j][k];
                unsigned long long wr;
                asm("mov.b64 %0, {%1, %1};" : "=l"(wr) : "f"(w));
                asm("fma.rn.f32x2 %0, %1, %2, %0;" : "+l"(acc[j][0]) : "l"(xp0), "l"(wr));
                asm("fma.rn.f32x2 %0, %1, %2, %0;" : "+l"(acc[j][1]) : "l"(xp1), "l"(wr));
                asm("fma.rn.f32x2 %0, %1, %2, %0;" : "+l"(acc[j][2]) : "l"(xp2), "l"(wr));
                asm("fma.rn.f32x2 %0, %1, %2, %0;" : "+l"(acc[j][3]) : "l"(xp3), "l"(wr));
            }
        }
    }

    // Epilogue: unpack pairs, store 8 contiguous outputs per node.
#pragma unroll
    for (int i = 0; i < 4; i++) {
        int m0 = base + mt * 8 + 2 * i;
        float o0[8], o1[8];
#pragma unroll
        for (int j = 0; j < 8; j++) {
            float2 v = *(float2*)&acc[j][i];
            o0[j] = v.x;
            o1[j] = v.y;
        }
        if (m0 < N_NODES) {
            float4* p = (float4*)(out + (size_t)m0 * D + nt * 8);
            p[0] = make_float4(o0[0], o0[1], o0[2], o0[3]);
            p[1] = make_float4(o0[4], o0[5], o0[6], o0[7]);
        }
        if (m0 + 1 < N_NODES) {
            float4* p = (float4*)(out + (size_t)(m0 + 1) * D + nt * 8);
            p[0] = make_float4(o1[0], o1[1], o1[2], o1[3]);
            p[1] = make_float4(o1[4], o1[5], o1[6], o1[7]);
        }
    }
}

// ---------------------------------------------------------------------------
extern "C" void kernel_launch(void* const* d_in, const int* in_sizes, int n_in,
                              void* d_out, int out_size) {
    // Resolve inputs by element count (robust to metadata ordering).
    const float* feat = nullptr;
    const void*  ei   = nullptr;
    const float* ew   = nullptr;
    const float* W    = nullptr;
    const float* b    = nullptr;

    for (int i = 0; i < n_in; i++) {
        switch (in_sizes[i]) {
            case 6400000: feat = (const float*)d_in[i]; break;
            case 2000000: ei   = d_in[i];               break;
            case 1000000: ew   = (const float*)d_in[i]; break;
            case 4096:    W    = (const float*)d_in[i]; break;
            case 64:      b    = (const float*)d_in[i]; break;
        }
    }

    float* out = (float*)d_out;
    (void)out_size;

    probe_kernel<<<1, 32>>>((const unsigned int*)ei);

    const int init_total = N_NODES * (D / 4);
    init_kernel<<<(init_total + 255) / 256, 256>>>((const float4*)feat);

    const int scatter_lanes = N_EDGES * 16;
    scatter_kernel<<<(scatter_lanes + 255) / 256, 256>>>((const float4*)feat, ei, ew);

    gemm_kernel<<<(N_NODES + 127) / 128, 128>>>(W, b, out);
}